// round 11
// baseline (speedup 1.0000x reference)
#include <cuda_runtime.h>
#include <cuda_bf16.h>
#include <cstddef>
#include <cstdint>

#define DIMN   512
#define NSLOT  32
#define BATCH  32
#define TSTEPS 2048
#define RANKS  8
#define BPC    4
#define DCH    64
#define NTHR   512

__device__ float g_pre[(size_t)BATCH * TSTEPS * DIMN];
__device__ float g_WhP[DIMN * DIMN];   // packed: float4 idx = k4*DIMN + d
__device__ float g_WwP[DIMN * DIMN];

// ---------------- PTX helpers ----------------
__device__ __forceinline__ uint32_t smem_u32(const void* p) {
    uint32_t a;
    asm("{ .reg .u64 t; cvta.to.shared.u64 t, %1; cvt.u32.u64 %0, t; }"
        : "=r"(a) : "l"(p));
    return a;
}
__device__ __forceinline__ uint32_t mapa_rank(uint32_t laddr, uint32_t rank) {
    uint32_t r;
    asm("mapa.shared::cluster.u32 %0, %1, %2;" : "=r"(r) : "r"(laddr), "r"(rank));
    return r;
}
__device__ __forceinline__ void sts_cluster_f32(uint32_t addr, float v) {
    asm volatile("st.shared::cluster.f32 [%0], %1;" :: "r"(addr), "f"(v) : "memory");
}
__device__ __forceinline__ void sts_cluster_f32x2(uint32_t addr, float a, float b) {
    asm volatile("st.shared::cluster.v2.f32 [%0], {%1, %2};"
                 :: "r"(addr), "f"(a), "f"(b) : "memory");
}
__device__ __forceinline__ void mbar_init(uint32_t addr, uint32_t cnt) {
    asm volatile("mbarrier.init.shared.b64 [%0], %1;" :: "r"(addr), "r"(cnt) : "memory");
}
__device__ __forceinline__ void mbar_arrive_cl(uint32_t remAddr) {
    asm volatile("mbarrier.arrive.release.cluster.shared::cluster.b64 _, [%0];"
                 :: "r"(remAddr) : "memory");
}
__device__ __forceinline__ void mbar_wait_parity_cl(uint32_t addr, uint32_t parity) {
    asm volatile(
        "{\n\t"
        ".reg .pred P;\n\t"
        "LAB_WAIT_%=:\n\t"
        "mbarrier.try_wait.parity.acquire.cluster.shared::cta.b64 P, [%0], %1, 0x989680;\n\t"
        "@P bra.uni LAB_DONE_%=;\n\t"
        "bra.uni LAB_WAIT_%=;\n\t"
        "LAB_DONE_%=:\n\t"
        "}"
        :: "r"(addr), "r"(parity) : "memory");
}
__device__ __forceinline__ void cluster_sync_() {
    asm volatile("barrier.cluster.arrive.aligned;\n\tbarrier.cluster.wait.aligned;" ::: "memory");
}
#define GBAR(g) asm volatile("bar.sync %0, 256;" :: "r"(1 + (g)) : "memory")

__global__ void dummy_k() {}

// ---------------- weight packing ----------------
__global__ void pack_weights(const float* __restrict__ Wh,
                             const float* __restrict__ Ww) {
    int idx = blockIdx.x * blockDim.x + threadIdx.x;
    if (idx >= DIMN * DIMN) return;
    int d = idx / DIMN;
    int k = idx % DIMN;
    int dst = ((k >> 2) * DIMN + d) * 4 + (k & 3);
    g_WhP[dst] = Wh[idx];
    g_WwP[dst] = Ww[idx];
}

// ---------------- pre-GEMM ----------------
__global__ __launch_bounds__(256) void gemm_pre(
    const float* __restrict__ X,
    const float* __restrict__ W,
    const float* __restrict__ bias)
{
    __shared__ float As[8][128];
    __shared__ float Bs[8][64];
    const int tid = threadIdx.x;
    const int m0 = blockIdx.y * 128;
    const int n0 = blockIdx.x * 64;
    const int trow = tid >> 4;
    const int tcol = tid & 15;
    float acc[8][4];
#pragma unroll
    for (int i = 0; i < 8; ++i)
#pragma unroll
        for (int j = 0; j < 4; ++j) acc[i][j] = 0.f;
    const int a_m  = tid >> 1;
    const int a_k4 = (tid & 1) * 4;
    for (int k0 = 0; k0 < DIMN; k0 += 8) {
        float4 av = *reinterpret_cast<const float4*>(
            X + (size_t)(m0 + a_m) * DIMN + k0 + a_k4);
        As[a_k4 + 0][a_m] = av.x;
        As[a_k4 + 1][a_m] = av.y;
        As[a_k4 + 2][a_m] = av.z;
        As[a_k4 + 3][a_m] = av.w;
        if (tid < 128) {
            int bn  = tid >> 1;
            int bk4 = (tid & 1) * 4;
            float4 bv = *reinterpret_cast<const float4*>(
                W + (size_t)(n0 + bn) * DIMN + k0 + bk4);
            Bs[bk4 + 0][bn] = bv.x;
            Bs[bk4 + 1][bn] = bv.y;
            Bs[bk4 + 2][bn] = bv.z;
            Bs[bk4 + 3][bn] = bv.w;
        }
        __syncthreads();
#pragma unroll
        for (int kk = 0; kk < 8; ++kk) {
            float4 ra0 = *reinterpret_cast<const float4*>(&As[kk][trow * 8]);
            float4 ra1 = *reinterpret_cast<const float4*>(&As[kk][trow * 8 + 4]);
            float4 rb  = *reinterpret_cast<const float4*>(&Bs[kk][tcol * 4]);
            float ra[8] = {ra0.x, ra0.y, ra0.z, ra0.w, ra1.x, ra1.y, ra1.z, ra1.w};
            float rbv[4] = {rb.x, rb.y, rb.z, rb.w};
#pragma unroll
            for (int i = 0; i < 8; ++i)
#pragma unroll
                for (int j = 0; j < 4; ++j) acc[i][j] += ra[i] * rbv[j];
        }
        __syncthreads();
    }
    float4 bj = *reinterpret_cast<const float4*>(bias + n0 + tcol * 4);
#pragma unroll
    for (int i = 0; i < 8; ++i) {
        float4 v;
        v.x = acc[i][0] + bj.x;
        v.y = acc[i][1] + bj.y;
        v.z = acc[i][2] + bj.z;
        v.w = acc[i][3] + bj.w;
        *reinterpret_cast<float4*>(
            &g_pre[(size_t)(m0 + trow * 8 + i) * DIMN + n0 + tcol * 4]) = v;
    }
}

// ---------------- exact entmax-1.5 ----------------
__device__ __forceinline__ float entmax_coef(float raw, float* __restrict__ sb, int lane) {
    const unsigned FULL = 0xffffffffu;
    float z = raw * 0.5f;
    float m = z;
#pragma unroll
    for (int o = 16; o > 0; o >>= 1) m = fmaxf(m, __shfl_xor_sync(FULL, m, o));
    z -= m;
    int rank = 0;
#pragma unroll
    for (int j = 0; j < 32; ++j) {
        float zj = __shfl_sync(FULL, z, j);
        rank += (zj > z) || (zj == z && j < lane);
    }
    sb[rank] = z;
    __syncwarp();
    float zs = sb[lane];
    float cs = zs, cq = zs * zs;
#pragma unroll
    for (int o = 1; o < 32; o <<= 1) {
        float a  = __shfl_up_sync(FULL, cs, o);
        float bq = __shfl_up_sync(FULL, cq, o);
        if (lane >= o) { cs += a; cq += bq; }
    }
    float k    = (float)(lane + 1);
    float mean = cs / k;
    float msq  = cq / k;
    float ss   = k * (msq - mean * mean);
    float delta = fmaxf((1.f - ss) / k, 0.f);
    float tau   = mean - sqrtf(delta);
    unsigned sup = __ballot_sync(FULL, tau <= zs);
    int kstar = __popc(sup) - 1;
    float tau_star = __shfl_sync(FULL, tau, kstar);
    float p = fmaxf(z - tau_star, 0.f);
    return p * p;
}

// ---------------- SMEM float offsets ----------------
#define SM_WSM    0       // W_h slice [128 k4][64 dl] f4    32768
#define SM_PARTH  32768   // [2 grp][8 seg][2 b][64]          2048
#define SM_PARTW  34816   //                                  2048
#define SM_XW     36864   // [2 par][4 b][512]                4096
#define SM_WVEC   40960   // [4][64]                          256
#define SM_COEFA  41216   // [4][32]                          128
#define SM_COEFB  41344
#define SM_SORT   41472
#define SM_TAPE   41600   // [4][32][65]                      8320
#define SM_XC     49920   // [2 par][8 rk][4 b][66]           4224
#define SM_MB     54144   // 4 u64: B0,B1,C0,C1
#define SM_FLOATS 54152

__global__ void __launch_bounds__(NTHR, 1) __cluster_dims__(RANKS, 1, 1)
recur11(const float* __restrict__ tape0,
        const float* __restrict__ work0,
        float* __restrict__ out_hseq,
        float* __restrict__ out_tape,
        float* __restrict__ out_hlast)
{
    extern __shared__ float sm[];
    float* wsm    = sm + SM_WSM;
    float* part_h = sm + SM_PARTH;
    float* part_w = sm + SM_PARTW;
    float* xw     = sm + SM_XW;
    float* wvec   = sm + SM_WVEC;
    float* coefA  = sm + SM_COEFA;
    float* coefB  = sm + SM_COEFB;
    float* sortb  = sm + SM_SORT;
    float* tape   = sm + SM_TAPE;
    float* xc     = sm + SM_XC;

    const int tid  = threadIdx.x;
    const int lane = tid & 31;
    const int wid  = tid >> 5;
    const int g    = wid >> 3;        // group 0/1
    const int wg   = wid & 7;         // warp in group
    const int tidg = tid & 255;
    const int rk   = blockIdx.x & (RANKS - 1);
    const int bg   = blockIdx.x >> 3;
    const int b0   = bg * BPC;
    const int dbase = rk * DCH;
    const float invsd = 0.044194173824159216f;

    const uint32_t sbase = smem_u32(sm);
    const uint32_t a_xw  = sbase + SM_XW * 4u;
    const uint32_t a_xc  = sbase + SM_XC * 4u;
    const uint32_t a_mbB = sbase + (SM_MB + g * 2) * 4u;      // B0/B1
    const uint32_t a_mbC = sbase + (SM_MB + 4 + g * 2) * 4u;  // C0/C1

    if (tid == 0) {
#pragma unroll
        for (int i = 0; i < 4; ++i)
            mbar_init(sbase + (SM_MB + i * 2) * 4u, RANKS);
    }

    // ---- prologue loads (full CTA) ----
    for (int i = tid; i < BPC * NSLOT * DCH; i += NTHR) {
        int b = i >> 11, n = (i >> 6) & 31, d = i & 63;
        tape[(b * NSLOT + n) * 65 + d] =
            tape0[((size_t)(b0 + b) * NSLOT + n) * DIMN + dbase + d];
    }
    for (int i = tid; i < BPC * DIMN; i += NTHR) {
        int b = i >> 9, k = i & 511;
        xw[b * DIMN + k] = work0[(size_t)(b0 + b) * DIMN + k];
    }
    {
        float4* wsm4 = reinterpret_cast<float4*>(wsm);
        const float4* src = reinterpret_cast<const float4*>(g_WhP);
        for (int i = tid; i < 8192; i += NTHR)
            wsm4[i] = src[(size_t)(i >> 6) * DIMN + dbase + (i & 63)];
    }
    __syncthreads();
    cluster_sync_();

    // ---- group prologue: initial read-scores exchange (parity 0) ----
    if (wg < 2) {
        const int bb = 2 * g + wg;
        const float* tr = tape + (bb * NSLOT + lane) * 65;
        const float* wk = xw + bb * DIMN + dbase;
        float s = 0.f;
#pragma unroll
        for (int d = 0; d < DCH; ++d) s += tr[d] * wk[d];
        uint32_t off = a_xc + (unsigned)(rk * 264 + bb * 66 + 2 * lane) * 4u;
#pragma unroll
        for (int p = 0; p < RANKS; ++p) sts_cluster_f32(mapa_rank(off, p), s);
    }
    GBAR(g);
    if (tidg == 0) {
#pragma unroll
        for (int p = 0; p < RANKS; ++p) mbar_arrive_cl(mapa_rank(a_mbC, p));
    }
    mbar_wait_parity_cl(a_mbC, 0u);
    if (wg < 2) {
        const int bb = 2 * g + wg;
        float s = 0.f;
#pragma unroll
        for (int r = 0; r < RANKS; ++r) s += xc[r * 264 + bb * 66 + 2 * lane];
        coefA[bb * 32 + lane] = entmax_coef(s * invsd, sortb + bb * 32, lane);
    }

    // ---- group prologue: W_h GEMV on work0 -> part_h(g) ----
    {
        const float4* X4 = reinterpret_cast<const float4*>(xw);
        const float4* Wh4 = reinterpret_cast<const float4*>(wsm);
        float h00 = 0, h01 = 0, h10 = 0, h11 = 0;
#pragma unroll
        for (int i = 0; i < 16; ++i) {
            int k4 = wg * 16 + i;
            float4 w0 = Wh4[k4 * 64 + lane];
            float4 w1 = Wh4[k4 * 64 + 32 + lane];
            float4 x0 = X4[(2 * g) * 128 + k4];
            float4 x1 = X4[(2 * g + 1) * 128 + k4];
            h00 += w0.x*x0.x + w0.y*x0.y + w0.z*x0.z + w0.w*x0.w;
            h10 += w1.x*x0.x + w1.y*x0.y + w1.z*x0.z + w1.w*x0.w;
            h01 += w0.x*x1.x + w0.y*x1.y + w0.z*x1.z + w0.w*x1.w;
            h11 += w1.x*x1.x + w1.y*x1.y + w1.z*x1.z + w1.w*x1.w;
        }
        float* ph = part_h + g * 1024 + wg * 128;
        ph[lane] = h00; ph[lane + 32] = h10;
        ph[64 + lane] = h01; ph[96 + lane] = h11;
    }
    float pre_reg = 0.f;
    if (tidg < 128) {
        const int bb = 2 * g + (tidg >> 6), d = tidg & 63;
        pre_reg = __ldcs(&g_pre[((size_t)(b0 + bb) * TSTEPS) * DIMN + dbase + d]);
    }
    GBAR(g);

    for (int t = 0; t < TSTEPS; ++t) {
        const int ni = (t & 1) ^ 1;
        const int cp = (t + 1) & 1;
        const int bp = t & 1;

        // ---- FH: finish h(t) (tidg<128) ----
        if (tidg < 128) {
            const int bloc = tidg >> 6, bb = 2 * g + bloc, d = tidg & 63;
            float acc = pre_reg;
#pragma unroll
            for (int s = 0; s < 8; ++s) acc += part_h[g * 1024 + s * 128 + bloc * 64 + d];
            const float* tr = tape + bb * NSLOT * 65 + d;
            const float* cf = coefA + bb * 32;
#pragma unroll 8
            for (int n = 0; n < NSLOT; ++n) acc += cf[n] * tr[n * 65];
            float h = tanhf(acc);
            __stcs(&out_hseq[((size_t)(b0 + bb) * TSTEPS + t) * DIMN + dbase + d], h);
            uint32_t off = a_xw + (unsigned)(ni * 2048 + bb * DIMN + dbase + d) * 4u;
#pragma unroll
            for (int p = 0; p < RANKS; ++p) sts_cluster_f32(mapa_rank(off, p), h);
            int tn = (t + 1 < TSTEPS) ? t + 1 : t;
            pre_reg = __ldcs(&g_pre[((size_t)(b0 + bb) * TSTEPS + tn) * DIMN + dbase + d]);
        }
        GBAR(g);
        if (tidg == 0) {
#pragma unroll
            for (int p = 0; p < RANKS; ++p) mbar_arrive_cl(mapa_rank(a_mbB, p));
        }
        mbar_wait_parity_cl(a_mbB, (uint32_t)bp);

        // ---- G: fused dual GEMV on h(t), 8 warps, 2 batches ----
        {
            const float4* X4 = reinterpret_cast<const float4*>(xw + ni * 2048);
            const float4* Wh4 = reinterpret_cast<const float4*>(wsm);
            const float4* Ww4 = reinterpret_cast<const float4*>(g_WwP)
                                + (size_t)(wg * 16) * DIMN + dbase + lane;
            float h00 = 0, h01 = 0, h10 = 0, h11 = 0;
            float w00 = 0, w01 = 0, w10 = 0, w11 = 0;
#pragma unroll
            for (int i = 0; i < 16; ++i) {
                int k4 = wg * 16 + i;
                float4 a0 = Wh4[k4 * 64 + lane];
                float4 a1 = Wh4[k4 * 64 + 32 + lane];
                float4 c0 = __ldg(Ww4 + (size_t)i * DIMN);
                float4 c1 = __ldg(Ww4 + (size_t)i * DIMN + 32);
                float4 x0 = X4[(2 * g) * 128 + k4];
                float4 x1 = X4[(2 * g + 1) * 128 + k4];
                h00 += a0.x*x0.x + a0.y*x0.y + a0.z*x0.z + a0.w*x0.w;
                h10 += a1.x*x0.x + a1.y*x0.y + a1.z*x0.z + a1.w*x0.w;
                h01 += a0.x*x1.x + a0.y*x1.y + a0.z*x1.z + a0.w*x1.w;
                h11 += a1.x*x1.x + a1.y*x1.y + a1.z*x1.z + a1.w*x1.w;
                w00 += c0.x*x0.x + c0.y*x0.y + c0.z*x0.z + c0.w*x0.w;
                w10 += c1.x*x0.x + c1.y*x0.y + c1.z*x0.z + c1.w*x0.w;
                w01 += c0.x*x1.x + c0.y*x1.y + c0.z*x1.z + c0.w*x1.w;
                w11 += c1.x*x1.x + c1.y*x1.y + c1.z*x1.z + c1.w*x1.w;
            }
            float* ph = part_h + g * 1024 + wg * 128;
            ph[lane] = h00; ph[lane + 32] = h10;
            ph[64 + lane] = h01; ph[96 + lane] = h11;
            float* pw = part_w + g * 1024 + wg * 128;
            pw[lane] = w00; pw[lane + 32] = w10;
            pw[64 + lane] = w01; pw[96 + lane] = w11;
        }
        GBAR(g);

        // ---- SC: wvec reduce + scores + push (warps 0-1 of group) ----
        if (wg < 2) {
            const int bloc = wg, bb = 2 * g + bloc;
            float wv0 = 0.f, wv1 = 0.f;
#pragma unroll
            for (int s = 0; s < 8; ++s) {
                wv0 += part_w[g * 1024 + s * 128 + bloc * 64 + lane];
                wv1 += part_w[g * 1024 + s * 128 + bloc * 64 + 32 + lane];
            }
            wvec[bb * 64 + lane] = wv0;
            wvec[bb * 64 + 32 + lane] = wv1;
            __syncwarp();
            const float* tr = tape + (bb * NSLOT + lane) * 65;
            const float* wv = wvec + bb * 64;
            const float* hh = xw + ni * 2048 + bb * DIMN + dbase;
            float sA = 0.f, sB = 0.f;
#pragma unroll
            for (int d = 0; d < DCH; ++d) {
                float tv = tr[d];
                sA += tv * wv[d];
                sB += tv * hh[d];
            }
            float v = wv0 * hh[lane] + wv1 * hh[32 + lane];
#pragma unroll
            for (int o = 16; o > 0; o >>= 1) v += __shfl_xor_sync(0xffffffffu, v, o);
            uint32_t off = a_xc + (unsigned)(cp * 2112 + rk * 264 + bb * 66 + 2 * lane) * 4u;
#pragma unroll
            for (int p = 0; p < RANKS; ++p) sts_cluster_f32x2(mapa_rank(off, p), sA, sB);
            if (lane == 0) {
                uint32_t offc = a_xc + (unsigned)(cp * 2112 + rk * 264 + bb * 66 + 64) * 4u;
#pragma unroll
                for (int p = 0; p < RANKS; ++p) sts_cluster_f32(mapa_rank(offc, p), v);
            }
        }
        GBAR(g);
        if (tidg == 0) {
#pragma unroll
            for (int p = 0; p < RANKS; ++p) mbar_arrive_cl(mapa_rank(a_mbC, p));
        }
        mbar_wait_parity_cl(a_mbC, (uint32_t)cp);

        // ---- EN: beta + alpha(t+1) via score recurrence (warps 0-1) ----
        if (wg < 2) {
            const int bb = 2 * g + wg;
            const float* base = xc + cp * 2112 + bb * 66;
            float sA = 0.f, sB = 0.f, sC = 0.f;
#pragma unroll
            for (int r = 0; r < RANKS; ++r) {
                float2 pr = *reinterpret_cast<const float2*>(base + r * 264 + 2 * lane);
                sA += pr.x;
                sB += pr.y;
                sC += base[r * 264 + 64];
            }
            float beta = entmax_coef(sA * invsd, sortb + bb * 32, lane);
            coefB[bb * 32 + lane] = beta;
            float rnext = ((1.f - beta) * sB + beta * sC) * invsd;
            coefA[bb * 32 + lane] = entmax_coef(rnext, sortb + bb * 32, lane);
        }
        GBAR(g);

        // ---- TU: tape convex update (8 warps: bloc = wg&1, 8-slot group) ----
        {
            const int bloc = wg & 1, bb = 2 * g + bloc;
            const int n0 = (wg >> 1) * 8;
            const float* wv = wvec + bb * 64;
            const float* cf = coefB + bb * 32 + n0;
            float* tb = tape + (bb * NSLOT + n0) * 65;
#pragma unroll
            for (int n = 0; n < 8; ++n) {
                float bt = cf[n], omb = 1.f - bt;
                float* row = tb + n * 65;
                row[lane]      = row[lane]      * omb + bt * wv[lane];
                row[lane + 32] = row[lane + 32] * omb + bt * wv[lane + 32];
            }
        }
        GBAR(g);
    }

    // ---- final outputs ----
    __syncthreads();
    for (int i = tid; i < BPC * NSLOT * DCH; i += NTHR) {
        int b = i >> 11, n = (i >> 6) & 31, d = i & 63;
        out_tape[((size_t)(b0 + b) * NSLOT + n) * DIMN + dbase + d] =
            tape[(b * NSLOT + n) * 65 + d];
    }
    if (tid < 256) {
        const int b = tid >> 6, d = tid & 63;
        out_hlast[(size_t)(b0 + b) * DIMN + dbase + d] = xw[b * DIMN + dbase + d];
    }
    cluster_sync_();
}

// ---------------- launch ----------------
extern "C" void kernel_launch(void* const* d_in, const int* in_sizes, int n_in,
                              void* d_out, int out_size) {
    const float* x     = (const float*)d_in[0];
    const float* tape0 = (const float*)d_in[1];
    const float* work0 = (const float*)d_in[2];
    const float* Wh    = (const float*)d_in[3];
    const float* Wx    = (const float*)d_in[4];
    const float* bh    = (const float*)d_in[5];
    const float* Ww    = (const float*)d_in[6];

    float* out       = (float*)d_out;
    float* out_hseq  = out;
    float* out_tape  = out + (size_t)BATCH * TSTEPS * DIMN;
    float* out_hlast = out_tape + (size_t)BATCH * NSLOT * DIMN;

    dummy_k<<<1, 32>>>();

    pack_weights<<<(DIMN * DIMN + 511) / 512, 512>>>(Wh, Ww);

    dim3 ggrid(DIMN / 64, (BATCH * TSTEPS) / 128);
    gemm_pre<<<ggrid, 256>>>(x, Wx, bh);

    const int smem_bytes = SM_FLOATS * 4;
    cudaFuncSetAttribute(recur11, cudaFuncAttributeMaxDynamicSharedMemorySize, smem_bytes);
    recur11<<<(BATCH / BPC) * RANKS, NTHR, smem_bytes>>>(
        tape0, work0, out_hseq, out_tape, out_hlast);
}